// round 16
// baseline (speedup 1.0000x reference)
#include <cuda_runtime.h>
#include <cuda_bf16.h>
#include <math.h>
#include <stdint.h>

#define BATCH 4096
#define DIM   768
#define TINV  20.0f
#define EPSV  1e-6f
#define SLOTS 128
#define FXSCALE 16384.0f
#define FXINV  (1.0f / 16384.0f)

#define BM 128
#define BN 128
#define BK 64
#define KPAD 72                        // bf16 elems per smem row (144 B)
#define ROWB (KPAD * 2)                // 144
#define STAGE_BYTES (128 * ROWB)       // 18432
#define STAGES 3
#define CHUNKS (DIM / BK)              // 12
#define NTILES 2576

#define PREP_GRID (128 + 3 * BATCH / 8)   // 1664

// dynamic smem layout (k_gemm)
#define OFF_A 0
#define OFF_B (STAGES * STAGE_BYTES)
#define OFF_TGT (2 * STAGES * STAGE_BYTES)
#define OFF_RNK (OFF_TGT + 512)
#define SMEM_DYN (OFF_RNK + 512)

// ---------------- device scratch ----------------
__device__ __align__(16) __nv_bfloat16 g_b[3ULL * BATCH * DIM];
__device__ int   g_tgt[BATCH];
__device__ int   g_rank[BATCH];
__device__ int   g_cnt[128];
// fixed-point row accumulators: [row][q], q: 0..2 = tot(mat), 3..5 = dif(mat)
__device__ unsigned long long g_S[(size_t)BATCH * 8];
__device__ float g_sval[3ULL * BATCH * SLOTS];
__device__ float g_blk[BATCH * 2];
__device__ int   g_done;

// ---------------- helpers ----------------
__device__ __forceinline__ uint32_t smem_u32(const void* p) {
    uint32_t a;
    asm("{ .reg .u64 t; cvta.to.shared.u64 t, %1; cvt.u32.u64 %0, t; }" : "=r"(a) : "l"(p));
    return a;
}
__device__ __forceinline__ void cpa16(uint32_t s, const void* g) {
    asm volatile("cp.async.cg.shared.global [%0], [%1], 16;" :: "r"(s), "l"(g) : "memory");
}
__device__ __forceinline__ void ldsm4(uint32_t* r, uint32_t addr) {
    asm volatile("ldmatrix.sync.aligned.m8n8.x4.shared.b16 {%0,%1,%2,%3}, [%4];"
                 : "=r"(r[0]), "=r"(r[1]), "=r"(r[2]), "=r"(r[3]) : "r"(addr));
}
__device__ __forceinline__ void mma_bf16(float* c, const uint32_t* a, uint32_t b0, uint32_t b1) {
    asm volatile(
        "mma.sync.aligned.m16n8k16.row.col.f32.bf16.bf16.f32 "
        "{%0,%1,%2,%3}, {%4,%5,%6,%7}, {%8,%9}, {%0,%1,%2,%3};"
        : "+f"(c[0]), "+f"(c[1]), "+f"(c[2]), "+f"(c[3])
        : "r"(a[0]), "r"(a[1]), "r"(a[2]), "r"(a[3]), "r"(b0), "r"(b1));
}
__device__ __forceinline__ unsigned long long f2fx(float v) {
    return (unsigned long long)__float2ll_rn(v * FXSCALE);
}
__device__ __forceinline__ void decode_tile(int id, int& mat, int& x, int& yt) {
    if (id < 528) {
        mat = 0;
        int rem = id, b = 0;
        while (rem > b) { rem -= (b + 1); b++; }
        yt = b; x = rem;
    } else {
        int id2 = id - 528;
        mat = 1 + (id2 >> 10);
        x = id2 & 31;
        yt = (id2 & 1023) >> 5;
    }
}
// prefetch one 64-wide chunk of tile (mat,x,yt) into stage s
__device__ __forceinline__ void pf_chunk(int mat, int x, int yt, int kc, int s,
                                         uint32_t sAst, uint32_t sBst, int lrow, int lc) {
    const uint32_t so = s * STAGE_BYTES;
    const __nv_bfloat16* gAp = g_b + ((size_t)(x * 128 + lrow)) * DIM + lc * 8 + kc * BK;
    const __nv_bfloat16* gBp = g_b + ((size_t)(mat * BATCH + yt * 128 + lrow)) * DIM + lc * 8 + kc * BK;
#pragma unroll
    for (int it = 0; it < 4; it++) {
        cpa16(sAst + so + it * 32 * ROWB, gAp + (size_t)it * 32 * DIM);
        cpa16(sBst + so + it * 32 * ROWB, gBp + (size_t)it * 32 * DIM);
    }
}

// ---------------- fused prep (unchanged from round 15) ----------------
__global__ __launch_bounds__(256) void k_prep(const float* f0, const float* f1,
                                              const float* f2, const int* t32) {
    const int t = threadIdx.x, wid = t >> 5, lane = t & 31;

    for (int k = blockIdx.x * 256 + t; k < BATCH * 8; k += PREP_GRID * 256)
        g_S[k] = 0ULL;

    if (blockIdx.x < 128) {
        __shared__ int flag;
        __shared__ int wcnt[8];
        if (t == 0) flag = 0;
        if (blockIdx.x == 0 && t == 0) g_done = 0;
        __syncthreads();
        for (int idx = t; idx < BATCH / 2; idx += 256)
            if (t32[2 * idx + 1] != 0) atomicOr(&flag, 1);
        __syncthreads();
        const bool is64 = (flag == 0);

        if (blockIdx.x == 0)
            for (int i = t; i < BATCH; i += 256) g_tgt[i] = is64 ? t32[2 * i] : t32[i];

        const int l = blockIdx.x;
        const int seg = wid * 512;
        const unsigned ltmask = (1u << lane) - 1;

        int cnt = 0;
#pragma unroll
        for (int b = 0; b < 16; b++) {
            int j = seg + b * 32 + lane;
            int tv = is64 ? t32[2 * j] : t32[j];
            unsigned bal = __ballot_sync(~0u, tv == l);
            cnt += __popc(bal);
        }
        if (lane == 0) wcnt[wid] = cnt;
        __syncthreads();

        int off = 0;
        for (int w = 0; w < wid; w++) off += wcnt[w];

        int running = off;
#pragma unroll
        for (int b = 0; b < 16; b++) {
            int j = seg + b * 32 + lane;
            int tv = is64 ? t32[2 * j] : t32[j];
            unsigned bal = __ballot_sync(~0u, tv == l);
            if (tv == l) {
                int r = running + __popc(bal & ltmask);
                g_rank[j] = r < SLOTS ? r : SLOTS - 1;
            }
            running += __popc(bal);
        }
        if (t == 0) {
            int s = 0;
            for (int w = 0; w < 8; w++) s += wcnt[w];
            g_cnt[l] = s;
        }
    } else {
        const int gid = (blockIdx.x - 128) * 8 + wid;
        const int row = gid & (BATCH - 1);
        const int mat = gid >> 12;
        const float* src = (mat == 0) ? f0 : ((mat == 1) ? f1 : f2);
        const float4* r4 = (const float4*)(src + (size_t)row * DIM);
        float4 v[6];
        float s = 0.f;
#pragma unroll
        for (int u = 0; u < 6; u++) {
            v[u] = r4[lane + 32 * u];
            s += v[u].x * v[u].x + v[u].y * v[u].y + v[u].z * v[u].z + v[u].w * v[u].w;
        }
#pragma unroll
        for (int o = 16; o; o >>= 1) s += __shfl_xor_sync(~0u, s, o);
        const float inv = rsqrtf(s);
        uint2* dst = (uint2*)(g_b + ((size_t)mat * BATCH + row) * DIM);
#pragma unroll
        for (int u = 0; u < 6; u++) {
            __nv_bfloat162 lo(__float2bfloat16(v[u].x * inv), __float2bfloat16(v[u].y * inv));
            __nv_bfloat162 hi(__float2bfloat16(v[u].z * inv), __float2bfloat16(v[u].w * inv));
            uint2 pk;
            pk.x = *(uint32_t*)&lo;
            pk.y = *(uint32_t*)&hi;
            dst[lane + 32 * u] = pk;
        }
    }
}

// ---------------- persistent HMMA GEMM + fused exp epilogue ----------------
// grid = 2 x SM count; each CTA strides over the 2576 tiles. Cross-tile
// prefetch: the two empty commit slots (kc=10,11) load the NEXT tile's
// chunks 0,1, so the cp.async pipeline never drains.
__global__ __launch_bounds__(256, 2) void k_gemm() {
    extern __shared__ __align__(1024) char smem[];
    const int t = threadIdx.x, wid = t >> 5, lane = t & 31;
    const int wm = (wid >> 1) * 32;
    const int wn = (wid & 1) * 64;

    int* stgt = (int*)(smem + OFF_TGT);
    int* srnk = (int*)(smem + OFF_RNK);

    const uint32_t sb = smem_u32(smem);
    const int lrow = t >> 3, lc = t & 7;
    const uint32_t sAst = sb + OFF_A + lrow * ROWB + lc * 16;
    const uint32_t sBst = sb + OFF_B + lrow * ROWB + lc * 16;
    const uint32_t afrag = sb + OFF_A + (wm + (lane & 15)) * ROWB + (lane >> 4) * 16;
    const uint32_t bfrag = sb + OFF_B + (wn + (lane & 15)) * ROWB + (lane >> 4) * 16;

    int id = blockIdx.x;
    int mat, x, yt;
    decode_tile(id, mat, x, yt);

    // initial prefetch: chunks 0,1 of first tile
    pf_chunk(mat, x, yt, 0, 0, sAst, sBst, lrow, lc);
    asm volatile("cp.async.commit_group;");
    pf_chunk(mat, x, yt, 1, 1, sAst, sBst, lrow, lc);
    asm volatile("cp.async.commit_group;");

    while (true) {
        const int nid = id + gridDim.x;
        const bool hasN = (nid < NTILES);
        int nmat, nx, nyt;
        if (hasN) decode_tile(nid, nmat, nx, nyt);

        const int i0 = x << 7;
        const int j0 = yt << 7;

        __syncthreads();   // previous epilogue done reading stgt/srnk
        if (t < 128) { stgt[t] = g_tgt[j0 + t]; srnk[t] = g_rank[j0 + t]; }

        float c[2][8][4];
#pragma unroll
        for (int mt = 0; mt < 2; mt++)
#pragma unroll
            for (int nt = 0; nt < 8; nt++)
#pragma unroll
                for (int v = 0; v < 4; v++) c[mt][nt][v] = 0.f;

        int st = 0, stn = 2;
        for (int kc = 0; kc < CHUNKS; kc++) {
            asm volatile("cp.async.wait_group 1;");
            __syncthreads();
            if (kc + 2 < CHUNKS) {
                pf_chunk(mat, x, yt, kc + 2, stn, sAst, sBst, lrow, lc);
            } else if (hasN) {
                pf_chunk(nmat, nx, nyt, kc + 2 - CHUNKS, stn, sAst, sBst, lrow, lc);
            }
            asm volatile("cp.async.commit_group;");

            const uint32_t af = afrag + st * STAGE_BYTES;
            const uint32_t bf = bfrag + st * STAGE_BYTES;
#pragma unroll
            for (int ks = 0; ks < 4; ks++) {
                uint32_t a0[4], a1[4], b[4][4];
                ldsm4(a0, af + ks * 32);
                ldsm4(a1, af + 16 * ROWB + ks * 32);
#pragma unroll
                for (int np = 0; np < 4; np++)
                    ldsm4(b[np], bf + np * 16 * ROWB + ks * 32);
#pragma unroll
                for (int np = 0; np < 4; np++) {
                    mma_bf16(c[0][2 * np + 0], a0, b[np][0], b[np][2]);
                    mma_bf16(c[0][2 * np + 1], a0, b[np][1], b[np][3]);
                    mma_bf16(c[1][2 * np + 0], a1, b[np][0], b[np][2]);
                    mma_bf16(c[1][2 * np + 1], a1, b[np][1], b[np][3]);
                }
            }
            st = (st == STAGES - 1) ? 0 : st + 1;
            stn = (stn == STAGES - 1) ? 0 : stn + 1;
        }

        // ---- fused epilogue (fixed-point atomic row sums) ----
        const bool sym = (mat == 0) && (x != yt);

        float tcol[8][2], dcol[8][2];
#pragma unroll
        for (int nt = 0; nt < 8; nt++) { tcol[nt][0] = tcol[nt][1] = 0.f; dcol[nt][0] = dcol[nt][1] = 0.f; }

#pragma unroll
        for (int mt = 0; mt < 2; mt++) {
            const int i_lo = i0 + wm + mt * 16 + (lane >> 2);
            const int i_hi = i_lo + 8;
            const int t_lo = g_tgt[i_lo];
            const int t_hi = g_tgt[i_hi];
            const int ri_lo = g_rank[i_lo];
            const int ri_hi = g_rank[i_hi];
            float tlo = 0.f, thi = 0.f, dlo = 0.f, dhi = 0.f;
#pragma unroll
            for (int nt = 0; nt < 8; nt++) {
#pragma unroll
                for (int v = 0; v < 2; v++) {
                    const int j = wn + nt * 8 + (lane & 3) * 2 + v;
                    const int tj = stgt[j];
                    const int rk = srnk[j];
                    float e0 = __expf(TINV * c[mt][nt][v]);
                    float e1 = __expf(TINV * c[mt][nt][2 + v]);
                    tlo += e0; thi += e1;
                    if (t_lo != tj) dlo += e0;
                    else {
                        g_sval[((size_t)mat * BATCH + i_lo) * SLOTS + rk] = e0;
                        if (sym) g_sval[(size_t)(j0 + j) * SLOTS + ri_lo] = e0;
                    }
                    if (t_hi != tj) dhi += e1;
                    else {
                        g_sval[((size_t)mat * BATCH + i_hi) * SLOTS + rk] = e1;
                        if (sym) g_sval[(size_t)(j0 + j) * SLOTS + ri_hi] = e1;
                    }
                    if (sym) {
                        tcol[nt][v] += e0 + e1;
                        dcol[nt][v] += (t_lo != tj ? e0 : 0.f) + (t_hi != tj ? e1 : 0.f);
                    }
                }
            }
#pragma unroll
            for (int o = 1; o <= 2; o <<= 1) {
                tlo += __shfl_xor_sync(~0u, tlo, o);
                thi += __shfl_xor_sync(~0u, thi, o);
                dlo += __shfl_xor_sync(~0u, dlo, o);
                dhi += __shfl_xor_sync(~0u, dhi, o);
            }
            if ((lane & 3) == 0) {
                atomicAdd(&g_S[(size_t)i_lo * 8 + mat], f2fx(tlo));
                atomicAdd(&g_S[(size_t)i_hi * 8 + mat], f2fx(thi));
                atomicAdd(&g_S[(size_t)i_lo * 8 + 3 + mat], f2fx(dlo));
                atomicAdd(&g_S[(size_t)i_hi * 8 + 3 + mat], f2fx(dhi));
            }
        }

        if (sym) {
#pragma unroll
            for (int nt = 0; nt < 8; nt++)
#pragma unroll
                for (int v = 0; v < 2; v++)
#pragma unroll
                    for (int o = 4; o <= 16; o <<= 1) {
                        tcol[nt][v] += __shfl_xor_sync(~0u, tcol[nt][v], o);
                        dcol[nt][v] += __shfl_xor_sync(~0u, dcol[nt][v], o);
                    }
            if (lane < 4) {
#pragma unroll
                for (int nt = 0; nt < 8; nt++)
#pragma unroll
                    for (int v = 0; v < 2; v++) {
                        const int j = j0 + wn + nt * 8 + lane * 2 + v;
                        atomicAdd(&g_S[(size_t)j * 8 + 0], f2fx(tcol[nt][v]));
                        atomicAdd(&g_S[(size_t)j * 8 + 3], f2fx(dcol[nt][v]));
                    }
            }
        }

        if (!hasN) break;
        id = nid; mat = nmat; x = nx; yt = nyt;
    }
}

// ---------------- per-row log terms (warp per row) + fused final ----------------
__global__ __launch_bounds__(256) void k_terms(float* out) {
    const int wid = threadIdx.x >> 5, lane = threadIdx.x & 31;
    const int i = blockIdx.x * 8 + wid;
    float sv = 0.f;
    if (lane < 6) sv = (float)(long long)g_S[(size_t)i * 8 + lane] * FXINV;
    const float S0 = __shfl_sync(~0u, sv, 0);
    const float S1 = __shfl_sync(~0u, sv, 1);
    const float S2 = __shfl_sync(~0u, sv, 2);
    const float D0 = __shfl_sync(~0u, sv, 3);
    const float D1 = __shfl_sync(~0u, sv, 4);
    const float D2 = __shfl_sync(~0u, sv, 5);
    const float dco = D0 + D2 + S1 + EPSV;
    const float dad = D1 + S2 + S0 + EPSV;
    int cnt = g_cnt[g_tgt[i]];
    if (cnt > SLOTS) cnt = SLOTS;
    const float* v0 = &g_sval[((size_t)0 * BATCH + i) * SLOTS];
    const float* v1 = &g_sval[((size_t)1 * BATCH + i) * SLOTS];
    const float* v2 = &g_sval[((size_t)2 * BATCH + i) * SLOTS];
    float co = 0.f, ad = 0.f;
    for (int s = lane; s < cnt; s += 32) {
        float e0 = v0[s], e1 = v1[s], e2 = v2[s];
        co -= __logf(e0 / (e0 + dco) + EPSV);
        co -= __logf(e2 / (e2 + dco) + EPSV);
        ad -= __logf(e1 / (e1 + dad) + EPSV);
    }
#pragma unroll
    for (int o = 16; o; o >>= 1) {
        co += __shfl_xor_sync(~0u, co, o);
        ad += __shfl_xor_sync(~0u, ad, o);
    }
    if (lane == 0) {
        g_blk[i * 2 + 0] = ad;
        g_blk[i * 2 + 1] = co;
    }

    __threadfence();
    __shared__ int amLast;
    if (threadIdx.x == 0) amLast = (atomicAdd(&g_done, 1) == gridDim.x - 1);
    __syncthreads();
    if (amLast) {
        __shared__ float sha[256], shc[256];
        const int t = threadIdx.x;
        float a = 0.f, c = 0.f;
        for (int k = t; k < BATCH; k += 256) { a += g_blk[2 * k]; c += g_blk[2 * k + 1]; }
        sha[t] = a; shc[t] = c;
        __syncthreads();
        for (int o = 128; o; o >>= 1) {
            if (t < o) { sha[t] += sha[t + o]; shc[t] += shc[t + o]; }
            __syncthreads();
        }
        if (t == 0) {
            out[0] = sha[0] / (float)BATCH;
            out[1] = shc[0] / (float)BATCH;
        }
    }
}

// ---------------- launch ----------------
extern "C" void kernel_launch(void* const* d_in, const int* in_sizes, int n_in,
                              void* d_out, int out_size) {
    const float* feat     = (const float*)d_in[0];
    const float* feat_gen = (const float*)d_in[1];
    const float* feat_aug = (const float*)d_in[2];
    const int*   tgt_raw  = (const int*)d_in[3];
    float* out = (float*)d_out;

    static int persist_grid = 0;
    if (!persist_grid) {
        cudaFuncSetAttribute(k_gemm, cudaFuncAttributeMaxDynamicSharedMemorySize, SMEM_DYN);
        int sms = 0;
        cudaDeviceGetAttribute(&sms, cudaDevAttrMultiProcessorCount, 0);
        persist_grid = 2 * sms;
        if (persist_grid <= 0 || persist_grid > NTILES) persist_grid = 296;
    }

    k_prep<<<PREP_GRID, 256>>>(feat, feat_gen, feat_aug, tgt_raw);
    k_gemm<<<persist_grid, 256, SMEM_DYN>>>();
    k_terms<<<512, 256>>>(out);
}

// round 17
// speedup vs baseline: 1.1153x; 1.1153x over previous
#include <cuda_runtime.h>
#include <cuda_bf16.h>
#include <math.h>
#include <stdint.h>

#define BATCH 4096
#define DIM   768
#define TINV  20.0f
#define EPSV  1e-6f
#define SLOTS 128

#define BM 128
#define BN 128
#define BK 64
#define KPAD 72                        // bf16 elems per smem row (144 B)
#define ROWB (KPAD * 2)                // 144
#define STAGE_BYTES (128 * ROWB)       // 18432
#define STAGES 3
#define CHUNKS (DIM / BK)              // 12
#define NGROUP 384                     // mat0: 0..255, mat1: 256..319, mat2: 320..383

#define PREP_GRID (128 + 3 * BATCH / 8)   // 1664

// dynamic smem layout (k_gemm)
#define OFF_A 0
#define OFF_B (STAGES * STAGE_BYTES)
#define OFF_TGT (2 * STAGES * STAGE_BYTES)
#define OFF_RNK (OFF_TGT + 512)
#define SMEM_DYN (OFF_RNK + 512)

// ---------------- device scratch ----------------
__device__ __align__(16) __nv_bfloat16 g_b[3ULL * BATCH * DIM];
__device__ int   g_tgt[BATCH];
__device__ int   g_rank[BATCH];
__device__ int   g_cnt[128];
__device__ __align__(16) float g_tot[(size_t)BATCH * NGROUP];   // [row][group]
__device__ __align__(16) float g_dif[(size_t)BATCH * NGROUP];
__device__ float g_sval[3ULL * BATCH * SLOTS];
__device__ float g_blk[BATCH * 2];
__device__ int   g_done;

// ---------------- helpers ----------------
__device__ __forceinline__ uint32_t smem_u32(const void* p) {
    uint32_t a;
    asm("{ .reg .u64 t; cvta.to.shared.u64 t, %1; cvt.u32.u64 %0, t; }" : "=r"(a) : "l"(p));
    return a;
}
__device__ __forceinline__ void cpa16(uint32_t s, const void* g) {
    asm volatile("cp.async.cg.shared.global [%0], [%1], 16;" :: "r"(s), "l"(g) : "memory");
}
__device__ __forceinline__ void ldsm4(uint32_t* r, uint32_t addr) {
    asm volatile("ldmatrix.sync.aligned.m8n8.x4.shared.b16 {%0,%1,%2,%3}, [%4];"
                 : "=r"(r[0]), "=r"(r[1]), "=r"(r[2]), "=r"(r[3]) : "r"(addr));
}
__device__ __forceinline__ void mma_bf16(float* c, const uint32_t* a, uint32_t b0, uint32_t b1) {
    asm volatile(
        "mma.sync.aligned.m16n8k16.row.col.f32.bf16.bf16.f32 "
        "{%0,%1,%2,%3}, {%4,%5,%6,%7}, {%8,%9}, {%0,%1,%2,%3};"
        : "+f"(c[0]), "+f"(c[1]), "+f"(c[2]), "+f"(c[3])
        : "r"(a[0]), "r"(a[1]), "r"(a[2]), "r"(a[3]), "r"(b0), "r"(b1));
}

// ---------------- fused prep ----------------
// grid 1664: blocks <128 -> per-label ranks (segmented two-pass, 2 syncs);
//            blocks >=128 -> warp-per-row normalize. All blocks share zeroing.
__global__ __launch_bounds__(256) void k_prep(const float* f0, const float* f1,
                                              const float* f2, const int* t32) {
    const int t = threadIdx.x, wid = t >> 5, lane = t & 31;

    // zero mat0 group region (groups 0..255 of every row), spread over all blocks
    for (int k = blockIdx.x * 256 + t; k < 256 * BATCH; k += PREP_GRID * 256) {
        const int i = k >> 8, z = k & 255;
        g_tot[(size_t)i * NGROUP + z] = 0.f;
        g_dif[(size_t)i * NGROUP + z] = 0.f;
    }

    if (blockIdx.x < 128) {
        __shared__ int flag;
        __shared__ int wcnt[8];
        if (t == 0) flag = 0;
        if (blockIdx.x == 0 && t == 0) g_done = 0;
        __syncthreads();
        for (int idx = t; idx < BATCH / 2; idx += 256)
            if (t32[2 * idx + 1] != 0) atomicOr(&flag, 1);
        __syncthreads();
        const bool is64 = (flag == 0);

        if (blockIdx.x == 0)
            for (int i = t; i < BATCH; i += 256) g_tgt[i] = is64 ? t32[2 * i] : t32[i];

        const int l = blockIdx.x;
        const int seg = wid * 512;
        const unsigned ltmask = (1u << lane) - 1;

        // pass 1: per-warp match counts (no block syncs)
        int cnt = 0;
#pragma unroll
        for (int b = 0; b < 16; b++) {
            int j = seg + b * 32 + lane;
            int tv = is64 ? t32[2 * j] : t32[j];
            unsigned bal = __ballot_sync(~0u, tv == l);
            cnt += __popc(bal);
        }
        if (lane == 0) wcnt[wid] = cnt;
        __syncthreads();

        // exclusive offset for this warp
        int off = 0;
        for (int w = 0; w < wid; w++) off += wcnt[w];

        // pass 2: write ranks
        int running = off;
#pragma unroll
        for (int b = 0; b < 16; b++) {
            int j = seg + b * 32 + lane;
            int tv = is64 ? t32[2 * j] : t32[j];
            unsigned bal = __ballot_sync(~0u, tv == l);
            if (tv == l) {
                int r = running + __popc(bal & ltmask);
                g_rank[j] = r < SLOTS ? r : SLOTS - 1;
            }
            running += __popc(bal);
        }
        if (t == 0) {
            int s = 0;
            for (int w = 0; w < 8; w++) s += wcnt[w];
            g_cnt[l] = s;
        }
    } else {
        // warp-per-row normalize: gid in [0, 3*4096)
        const int gid = (blockIdx.x - 128) * 8 + wid;
        const int row = gid & (BATCH - 1);
        const int mat = gid >> 12;
        const float* src = (mat == 0) ? f0 : ((mat == 1) ? f1 : f2);
        const float4* r4 = (const float4*)(src + (size_t)row * DIM);
        float4 v[6];
        float s = 0.f;
#pragma unroll
        for (int u = 0; u < 6; u++) {
            v[u] = r4[lane + 32 * u];
            s += v[u].x * v[u].x + v[u].y * v[u].y + v[u].z * v[u].z + v[u].w * v[u].w;
        }
#pragma unroll
        for (int o = 16; o; o >>= 1) s += __shfl_xor_sync(~0u, s, o);
        const float inv = rsqrtf(s);
        uint2* dst = (uint2*)(g_b + ((size_t)mat * BATCH + row) * DIM);
#pragma unroll
        for (int u = 0; u < 6; u++) {
            __nv_bfloat162 lo(__float2bfloat16(v[u].x * inv), __float2bfloat16(v[u].y * inv));
            __nv_bfloat162 hi(__float2bfloat16(v[u].z * inv), __float2bfloat16(v[u].w * inv));
            uint2 pk;
            pk.x = *(uint32_t*)&lo;
            pk.y = *(uint32_t*)&hi;
            dst[lane + 32 * u] = pk;
        }
    }
}

// ---------------- HMMA GEMM + fused exp epilogue (symmetric mat0) ----------------
// 1D grid 2576: id<528 -> mat0 triangular (x<=yt); then 1024 mat1, 1024 mat2.
// 8 warps (256 threads), warp tile 32x64 as 4(m) x 2(n). 2 CTAs/SM.  [round-9 engine]
__global__ __launch_bounds__(256, 2) void k_gemm() {
    extern __shared__ __align__(1024) char smem[];
    const int t = threadIdx.x, wid = t >> 5, lane = t & 31;

    int mat, x, yt;
    {
        int id = blockIdx.x;
        if (id < 528) {
            mat = 0;
            int rem = id, b = 0;
            while (rem > b) { rem -= (b + 1); b++; }
            yt = b; x = rem;
        } else {
            int id2 = id - 528;
            mat = 1 + (id2 >> 10);
            x = id2 & 31;
            yt = (id2 & 1023) >> 5;
        }
    }
    const int i0 = x << 7;
    const int j0 = yt << 7;
    const int wm = (wid >> 1) * 32;
    const int wn = (wid & 1) * 64;

    int* stgt = (int*)(smem + OFF_TGT);
    int* srnk = (int*)(smem + OFF_RNK);
    if (t < 128) { stgt[t] = g_tgt[j0 + t]; srnk[t] = g_rank[j0 + t]; }

    const __nv_bfloat16* gA = g_b + (size_t)i0 * DIM;
    const __nv_bfloat16* gB = g_b + ((size_t)mat * BATCH + j0) * DIM;

    const uint32_t sb = smem_u32(smem);
    const int lrow = t >> 3, lc = t & 7;     // 8 thr/row, 32 rows/pass
    const uint32_t sAst = sb + OFF_A + lrow * ROWB + lc * 16;
    const uint32_t sBst = sb + OFF_B + lrow * ROWB + lc * 16;
    const __nv_bfloat16* gAp = gA + (size_t)lrow * DIM + lc * 8;
    const __nv_bfloat16* gBp = gB + (size_t)lrow * DIM + lc * 8;

    const uint32_t afrag = sb + OFF_A + (wm + (lane & 15)) * ROWB + (lane >> 4) * 16;
    const uint32_t bfrag = sb + OFF_B + (wn + (lane & 15)) * ROWB + (lane >> 4) * 16;

    float c[2][8][4];
#pragma unroll
    for (int mt = 0; mt < 2; mt++)
#pragma unroll
        for (int nt = 0; nt < 8; nt++)
#pragma unroll
            for (int v = 0; v < 4; v++) c[mt][nt][v] = 0.f;

#pragma unroll
    for (int s = 0; s < 2; s++) {
        const uint32_t so = s * STAGE_BYTES;
        const size_t go = (size_t)s * BK;
#pragma unroll
        for (int it = 0; it < 4; it++) {
            cpa16(sAst + so + it * 32 * ROWB, gAp + (size_t)it * 32 * DIM + go);
            cpa16(sBst + so + it * 32 * ROWB, gBp + (size_t)it * 32 * DIM + go);
        }
        asm volatile("cp.async.commit_group;");
    }

    int st = 0, stn = 2;
    for (int kc = 0; kc < CHUNKS; kc++) {
        asm volatile("cp.async.wait_group 1;");
        __syncthreads();
        if (kc + 2 < CHUNKS) {
            const uint32_t so = stn * STAGE_BYTES;
            const size_t go = (size_t)(kc + 2) * BK;
#pragma unroll
            for (int it = 0; it < 4; it++) {
                cpa16(sAst + so + it * 32 * ROWB, gAp + (size_t)it * 32 * DIM + go);
                cpa16(sBst + so + it * 32 * ROWB, gBp + (size_t)it * 32 * DIM + go);
            }
        }
        asm volatile("cp.async.commit_group;");

        const uint32_t af = afrag + st * STAGE_BYTES;
        const uint32_t bf = bfrag + st * STAGE_BYTES;
#pragma unroll
        for (int ks = 0; ks < 4; ks++) {
            uint32_t a0[4], a1[4], b[4][4];
            ldsm4(a0, af + ks * 32);
            ldsm4(a1, af + 16 * ROWB + ks * 32);
#pragma unroll
            for (int np = 0; np < 4; np++)
                ldsm4(b[np], bf + np * 16 * ROWB + ks * 32);
#pragma unroll
            for (int np = 0; np < 4; np++) {
                mma_bf16(c[0][2 * np + 0], a0, b[np][0], b[np][2]);
                mma_bf16(c[0][2 * np + 1], a0, b[np][1], b[np][3]);
                mma_bf16(c[1][2 * np + 0], a1, b[np][0], b[np][2]);
                mma_bf16(c[1][2 * np + 1], a1, b[np][1], b[np][3]);
            }
        }
        st = (st == STAGES - 1) ? 0 : st + 1;
        stn = (stn == STAGES - 1) ? 0 : stn + 1;
    }

    // ---- fused epilogue ----
    const bool sym = (mat == 0) && (x != yt);
    const int gd = (mat == 0) ? (yt * 8 + (wid & 1))
                              : (256 + (mat - 1) * 64 + yt * 2 + (wid & 1));

    float tcol[8][2], dcol[8][2];
#pragma unroll
    for (int nt = 0; nt < 8; nt++) { tcol[nt][0] = tcol[nt][1] = 0.f; dcol[nt][0] = dcol[nt][1] = 0.f; }

#pragma unroll
    for (int mt = 0; mt < 2; mt++) {
        const int i_lo = i0 + wm + mt * 16 + (lane >> 2);
        const int i_hi = i_lo + 8;
        const int t_lo = g_tgt[i_lo];
        const int t_hi = g_tgt[i_hi];
        const int ri_lo = g_rank[i_lo];
        const int ri_hi = g_rank[i_hi];
        float tlo = 0.f, thi = 0.f, dlo = 0.f, dhi = 0.f;
#pragma unroll
        for (int nt = 0; nt < 8; nt++) {
#pragma unroll
            for (int v = 0; v < 2; v++) {
                const int j = wn + nt * 8 + (lane & 3) * 2 + v;
                const int tj = stgt[j];
                const int rk = srnk[j];
                float e0 = __expf(TINV * c[mt][nt][v]);
                float e1 = __expf(TINV * c[mt][nt][2 + v]);
                tlo += e0; thi += e1;
                if (t_lo != tj) dlo += e0;
                else {
                    g_sval[((size_t)mat * BATCH + i_lo) * SLOTS + rk] = e0;
                    if (sym) g_sval[(size_t)(j0 + j) * SLOTS + ri_lo] = e0;
                }
                if (t_hi != tj) dhi += e1;
                else {
                    g_sval[((size_t)mat * BATCH + i_hi) * SLOTS + rk] = e1;
                    if (sym) g_sval[(size_t)(j0 + j) * SLOTS + ri_hi] = e1;
                }
                if (sym) {
                    tcol[nt][v] += e0 + e1;
                    dcol[nt][v] += (t_lo != tj ? e0 : 0.f) + (t_hi != tj ? e1 : 0.f);
                }
            }
        }
#pragma unroll
        for (int o = 1; o <= 2; o <<= 1) {
            tlo += __shfl_xor_sync(~0u, tlo, o);
            thi += __shfl_xor_sync(~0u, thi, o);
            dlo += __shfl_xor_sync(~0u, dlo, o);
            dhi += __shfl_xor_sync(~0u, dhi, o);
        }
        if ((lane & 3) == 0) {
            g_tot[(size_t)i_lo * NGROUP + gd] = tlo;
            g_tot[(size_t)i_hi * NGROUP + gd] = thi;
            g_dif[(size_t)i_lo * NGROUP + gd] = dlo;
            g_dif[(size_t)i_hi * NGROUP + gd] = dhi;
        }
    }

    if (sym) {
#pragma unroll
        for (int nt = 0; nt < 8; nt++)
#pragma unroll
            for (int v = 0; v < 2; v++)
#pragma unroll
                for (int o = 4; o <= 16; o <<= 1) {
                    tcol[nt][v] += __shfl_xor_sync(~0u, tcol[nt][v], o);
                    dcol[nt][v] += __shfl_xor_sync(~0u, dcol[nt][v], o);
                }
        if (lane < 4) {
            const int gt = x * 8 + 2 + (wid >> 1);
#pragma unroll
            for (int nt = 0; nt < 8; nt++)
#pragma unroll
                for (int v = 0; v < 2; v++) {
                    const int j = j0 + wn + nt * 8 + lane * 2 + v;
                    g_tot[(size_t)j * NGROUP + gt] = tcol[nt][v];
                    g_dif[(size_t)j * NGROUP + gt] = dcol[nt][v];
                }
        }
    }
}

// ---------------- per-row log terms (warp per row, float4) + fused final ----------------
__global__ __launch_bounds__(256) void k_terms(float* out) {
    const int wid = threadIdx.x >> 5, lane = threadIdx.x & 31;
    const int i = blockIdx.x * 8 + wid;      // grid 512 x 8 warps = 4096 rows
    const float4* rt4 = (const float4*)(g_tot + (size_t)i * NGROUP);   // 96 float4
    const float4* rd4 = (const float4*)(g_dif + (size_t)i * NGROUP);
    float4 ta = rt4[lane],      da = rd4[lane];        // mat0 f4 0..31
    float4 tb = rt4[32 + lane], db = rd4[32 + lane];   // mat0 f4 32..63
    float4 tc = rt4[64 + lane], dc = rd4[64 + lane];   // mat1 (lane<16) / mat2 (lane>=16)
    float S0 = ta.x + ta.y + ta.z + ta.w + tb.x + tb.y + tb.z + tb.w;
    float D0 = da.x + da.y + da.z + da.w + db.x + db.y + db.z + db.w;
    float s12 = tc.x + tc.y + tc.z + tc.w;
    float d12 = dc.x + dc.y + dc.z + dc.w;
    float S1 = (lane < 16) ? s12 : 0.f;
    float S2 = (lane < 16) ? 0.f : s12;
    float D1 = (lane < 16) ? d12 : 0.f;
    float D2 = (lane < 16) ? 0.f : d12;
#pragma unroll
    for (int o = 16; o; o >>= 1) {
        S0 += __shfl_xor_sync(~0u, S0, o);
        D0 += __shfl_xor_sync(~0u, D0, o);
        S1 += __shfl_xor_sync(~0u, S1, o);
        D1 += __shfl_xor_sync(~0u, D1, o);
        S2 += __shfl_xor_sync(~0u, S2, o);
        D2 += __shfl_xor_sync(~0u, D2, o);
    }
    const float dco = D0 + D2 + S1 + EPSV;
    const float dad = D1 + S2 + S0 + EPSV;
    int cnt = g_cnt[g_tgt[i]];
    if (cnt > SLOTS) cnt = SLOTS;
    const float* v0 = &g_sval[((size_t)0 * BATCH + i) * SLOTS];
    const float* v1 = &g_sval[((size_t)1 * BATCH + i) * SLOTS];
    const float* v2 = &g_sval[((size_t)2 * BATCH + i) * SLOTS];
    float co = 0.f, ad = 0.f;
    for (int s = lane; s < cnt; s += 32) {
        float e0 = v0[s], e1 = v1[s], e2 = v2[s];
        co -= __logf(e0 / (e0 + dco) + EPSV);
        co -= __logf(e2 / (e2 + dco) + EPSV);
        ad -= __logf(e1 / (e1 + dad) + EPSV);
    }
#pragma unroll
    for (int o = 16; o; o >>= 1) {
        co += __shfl_xor_sync(~0u, co, o);
        ad += __shfl_xor_sync(~0u, ad, o);
    }
    if (lane == 0) {
        g_blk[i * 2 + 0] = ad;
        g_blk[i * 2 + 1] = co;
    }

    __threadfence();
    __shared__ int amLast;
    if (threadIdx.x == 0) amLast = (atomicAdd(&g_done, 1) == gridDim.x - 1);
    __syncthreads();
    if (amLast) {
        __shared__ float sha[256], shc[256];
        const int t = threadIdx.x;
        float a = 0.f, c = 0.f;
        for (int k = t; k < BATCH; k += 256) { a += g_blk[2 * k]; c += g_blk[2 * k + 1]; }
        sha[t] = a; shc[t] = c;
        __syncthreads();
        for (int o = 128; o; o >>= 1) {
            if (t < o) { sha[t] += sha[t + o]; shc[t] += shc[t + o]; }
            __syncthreads();
        }
        if (t == 0) {
            out[0] = sha[0] / (float)BATCH;
            out[1] = shc[0] / (float)BATCH;
        }
    }
}

// ---------------- launch ----------------
extern "C" void kernel_launch(void* const* d_in, const int* in_sizes, int n_in,
                              void* d_out, int out_size) {
    const float* feat     = (const float*)d_in[0];
    const float* feat_gen = (const float*)d_in[1];
    const float* feat_aug = (const float*)d_in[2];
    const int*   tgt_raw  = (const int*)d_in[3];
    float* out = (float*)d_out;

    static int smem_set = 0;
    if (!smem_set) {
        cudaFuncSetAttribute(k_gemm, cudaFuncAttributeMaxDynamicSharedMemorySize, SMEM_DYN);
        smem_set = 1;
    }

    k_prep<<<PREP_GRID, 256>>>(feat, feat_gen, feat_aug, tgt_raw);
    k_gemm<<<2576, 256, SMEM_DYN>>>();
    k_terms<<<512, 256>>>(out);
}